// round 12
// baseline (speedup 1.0000x reference)
#include <cuda_runtime.h>
#include <cuda_bf16.h>
#include <cstdint>
#include <math.h>

#define BATCH 16384
#define NDIMS 64
#define NH 32
#define HID 512
#define NL 8

// ---------------------------------------------------------------------------
// Scratch (device globals; no allocations allowed)
// ---------------------------------------------------------------------------
__device__ __nv_bfloat16 g_a1hi[BATCH * 1024];      // h1 split hi  [m][1024]
__device__ __nv_bfloat16 g_a1lo[BATCH * 1024];
__device__ __nv_bfloat16 g_a2hi[BATCH * 1024];      // h2 split hi  [m][1024]
__device__ __nv_bfloat16 g_a2lo[BATCH * 1024];
__device__ __nv_bfloat16 g_w1hi[NL * 1024 * NH];    // W1^T split [l][n][k=32]
__device__ __nv_bfloat16 g_w1lo[NL * 1024 * NH];
__device__ __nv_bfloat16 g_w2hi[NL * 1024 * HID];   // W2^T split [l][n][k=512]
__device__ __nv_bfloat16 g_w2lo[NL * 1024 * HID];
__device__ __nv_bfloat16 g_w3hi[NL * 64 * HID];     // W3 dense [l][n=64][k=512]
__device__ __nv_bfloat16 g_w3lo[NL * 64 * HID];     //  rows 0-31: tW3^T, 32-63: sW3^T

// ---------------------------------------------------------------------------
// PTX helpers (sm_80-level features only: cp.async + mma.sync + ldmatrix)
// ---------------------------------------------------------------------------
__device__ __forceinline__ uint32_t smem_u32(const void* p) {
    uint32_t a;
    asm("{ .reg .u64 t; cvta.to.shared.u64 t, %1; cvt.u32.u64 %0, t; }" : "=r"(a) : "l"(p));
    return a;
}
__device__ __forceinline__ void cp16(uint32_t dst, const void* src) {
    asm volatile("cp.async.cg.shared.global [%0], [%1], 16;" :: "r"(dst), "l"(src));
}
#define CP_COMMIT() asm volatile("cp.async.commit_group;" ::: "memory")
#define CP_WAIT(n)  asm volatile("cp.async.wait_group %0;" :: "n"(n) : "memory")

// non-volatile: register-only op, lets ptxas schedule/interleave MMAs.
__device__ __forceinline__ void mma_bf16(float* d, const uint32_t* a, const uint32_t* b) {
    asm("mma.sync.aligned.m16n8k16.row.col.f32.bf16.bf16.f32 "
        "{%0,%1,%2,%3}, {%4,%5,%6,%7}, {%8,%9}, {%0,%1,%2,%3};"
        : "+f"(d[0]), "+f"(d[1]), "+f"(d[2]), "+f"(d[3])
        : "r"(a[0]), "r"(a[1]), "r"(a[2]), "r"(a[3]), "r"(b[0]), "r"(b[1]));
}
#define LDSM_X4(r0, r1, r2, r3, addr)                                          \
    asm volatile("ldmatrix.sync.aligned.m8n8.x4.shared.b16 {%0,%1,%2,%3}, [%4];" \
        : "=r"(r0), "=r"(r1), "=r"(r2), "=r"(r3) : "r"(addr))

__device__ __forceinline__ void split_bf16(float v, __nv_bfloat16& hi, __nv_bfloat16& lo) {
    hi = __float2bfloat16(v);
    lo = __float2bfloat16(v - __bfloat162float(hi));
}

#define ROWB 80                     // padded row stride in bytes (40 halves)

// ---------------------------------------------------------------------------
// Init: z = y, log_det = 0
// ---------------------------------------------------------------------------
__global__ void k_init(const float* __restrict__ y, float* __restrict__ out) {
    int i = blockIdx.x * blockDim.x + threadIdx.x;
    if (i < BATCH * NDIMS) {
        out[i] = y[i];
        out[BATCH * NDIMS + i] = 0.0f;
    }
}

// ---------------------------------------------------------------------------
// Weight pre-splits
// ---------------------------------------------------------------------------
__global__ __launch_bounds__(256) void k_split_w1(const float* __restrict__ tW1,
                                                  const float* __restrict__ sW1) {
    int i = blockIdx.x * 256 + threadIdx.x;
    if (i >= NL * 1024 * NH) return;
    int l = i / (1024 * NH);
    int rem = i - l * 1024 * NH;
    int n = rem / NH;
    int k = rem - n * NH;
    const float* W = (n < HID) ? tW1 : sW1;
    int nn = (n < HID) ? n : n - HID;
    float v = W[(size_t)l * NH * HID + k * HID + nn];
    split_bf16(v, g_w1hi[i], g_w1lo[i]);
}

__global__ __launch_bounds__(256) void k_split_w2(const float* __restrict__ tW2,
                                                  const float* __restrict__ sW2) {
    int i = blockIdx.x * 256 + threadIdx.x;
    if (i >= NL * 1024 * HID) return;
    int l = i / (1024 * HID);
    int rem = i - l * 1024 * HID;
    int n = rem / HID;
    int k = rem - n * HID;
    const float* W = (n < HID) ? tW2 : sW2;
    int nn = (n < HID) ? n : n - HID;
    float v = W[(size_t)l * HID * HID + k * HID + nn];
    split_bf16(v, g_w2hi[i], g_w2lo[i]);
}

// W3 dense: [l][n=64][k=512]; n<32 -> tW3[k][n], n>=32 -> sW3[k][n-32]
__global__ __launch_bounds__(256) void k_split_w3(const float* __restrict__ tW3,
                                                  const float* __restrict__ sW3) {
    int i = blockIdx.x * 256 + threadIdx.x;
    if (i >= NL * 64 * HID) return;
    int l = i / (64 * HID);
    int rem = i - l * 64 * HID;
    int n = rem / HID;
    int k = rem - n * HID;
    float v = (n < NH) ? tW3[(size_t)l * HID * NH + k * NH + n]
                       : sW3[(size_t)l * HID * NH + k * NH + (n - NH)];
    __nv_bfloat16 hi, lo;
    split_bf16(v, hi, lo);
    g_w3hi[i] = hi;
    g_w3lo[i] = lo;
}

// ---------------------------------------------------------------------------
// FC1 via mma.sync bf16x3 (standalone, layer 0 only): h1 = relu(z1@W1+b1)
// CTA: 256 thr, tile M=128 x N=128, K=32 single-shot. grid: (BATCH/128, 8)
// ---------------------------------------------------------------------------
__global__ __launch_bounds__(256) void k_fc1_mma(
    const float* __restrict__ zbuf,
    const float* __restrict__ tb1, const float* __restrict__ sb1,
    int layer, int i1off)
{
    __shared__ __align__(16) char sAh[128 * ROWB];
    __shared__ __align__(16) char sAl[128 * ROWB];
    __shared__ __align__(16) char sBh[128 * ROWB];
    __shared__ __align__(16) char sBl[128 * ROWB];

    const int tid = threadIdx.x;
    const int wid = tid >> 5, lane = tid & 31;
    const int wm = wid >> 1, wn = wid & 1;
    const int qr = lane >> 2, qc = lane & 3;
    const int lr = lane & 7, lg = lane >> 3;

    const int m0 = blockIdx.x * 128;
    const int n0 = blockIdx.y * 128;

    for (int idx = tid; idx < 128 * 32; idx += 256) {
        int r = idx >> 5, k = idx & 31;
        float v = zbuf[(m0 + r) * NDIMS + 2 * k + i1off];
        __nv_bfloat16 hi, lo;
        split_bf16(v, hi, lo);
        *(__nv_bfloat16*)(sAh + r * ROWB + k * 2) = hi;
        *(__nv_bfloat16*)(sAl + r * ROWB + k * 2) = lo;
    }
    {
        const __nv_bfloat16* bh = g_w1hi + ((size_t)layer * 1024 + n0) * NH;
        const __nv_bfloat16* bl = g_w1lo + ((size_t)layer * 1024 + n0) * NH;
        for (int idx = tid; idx < 128 * 4; idx += 256) {
            int r = idx >> 2, seg = idx & 3;
            *(uint4*)(sBh + r * ROWB + seg * 16) = *(const uint4*)(bh + r * NH + seg * 8);
            *(uint4*)(sBl + r * ROWB + seg * 16) = *(const uint4*)(bl + r * NH + seg * 8);
        }
    }
    __syncthreads();

    const uint32_t ah = smem_u32(sAh), al = smem_u32(sAl);
    const uint32_t bh = smem_u32(sBh), bl = smem_u32(sBl);
    const uint32_t aOff = (uint32_t)(wm * 32 + lr + (lg & 1) * 8) * ROWB + (lg >> 1) * 16;
    const uint32_t bOff = (uint32_t)(wn * 64 + lr + (lg >> 1) * 8) * ROWB + (lg & 1) * 16;

    float acc[2][8][4];
    #pragma unroll
    for (int mf = 0; mf < 2; mf++)
        #pragma unroll
        for (int nf = 0; nf < 8; nf++)
            #pragma unroll
            for (int j = 0; j < 4; j++) acc[mf][nf][j] = 0.0f;

    #pragma unroll
    for (int ks = 0; ks < 2; ks++) {
        const uint32_t ko = ks * 32;
        uint32_t Ah[2][4], Al[2][4];
        #pragma unroll
        for (int mf = 0; mf < 2; mf++) {
            uint32_t ra = aOff + mf * 16 * ROWB + ko;
            LDSM_X4(Ah[mf][0], Ah[mf][1], Ah[mf][2], Ah[mf][3], ah + ra);
            LDSM_X4(Al[mf][0], Al[mf][1], Al[mf][2], Al[mf][3], al + ra);
        }
        #pragma unroll
        for (int np = 0; np < 4; np++) {
            uint32_t rb = bOff + np * 16 * ROWB + ko;
            uint32_t Bh[4], Bl[4];
            LDSM_X4(Bh[0], Bh[1], Bh[2], Bh[3], bh + rb);
            LDSM_X4(Bl[0], Bl[1], Bl[2], Bl[3], bl + rb);
            #pragma unroll
            for (int h = 0; h < 2; h++)
                #pragma unroll
                for (int mf = 0; mf < 2; mf++)
                    mma_bf16(acc[mf][np * 2 + h], Ah[mf], Bh + h * 2);
            #pragma unroll
            for (int h = 0; h < 2; h++)
                #pragma unroll
                for (int mf = 0; mf < 2; mf++)
                    mma_bf16(acc[mf][np * 2 + h], Ah[mf], Bl + h * 2);
            #pragma unroll
            for (int h = 0; h < 2; h++)
                #pragma unroll
                for (int mf = 0; mf < 2; mf++)
                    mma_bf16(acc[mf][np * 2 + h], Al[mf], Bh + h * 2);
        }
    }

    const float* bias = (n0 < HID) ? tb1 : sb1;
    const int nbase = ((n0 < HID) ? n0 : n0 - HID) + wn * 64;

    #pragma unroll
    for (int mf = 0; mf < 2; mf++) {
        int r0 = m0 + wm * 32 + mf * 16 + qr;
        #pragma unroll
        for (int nf = 0; nf < 8; nf++) {
            int c = nf * 8 + qc * 2;
            float b0 = bias[nbase + c], b1 = bias[nbase + c + 1];
            int col = n0 + wn * 64 + c;
            #pragma unroll
            for (int half = 0; half < 2; half++) {
                int r = r0 + half * 8;
                float v0 = fmaxf(acc[mf][nf][half * 2 + 0] + b0, 0.0f);
                float v1 = fmaxf(acc[mf][nf][half * 2 + 1] + b1, 0.0f);
                __nv_bfloat16 h0, l0, h1, l1;
                split_bf16(v0, h0, l0);
                split_bf16(v1, h1, l1);
                __nv_bfloat162 ph; ph.x = h0; ph.y = h1;
                __nv_bfloat162 pl; pl.x = l0; pl.y = l1;
                *(__nv_bfloat162*)&g_a1hi[(size_t)r * 1024 + col] = ph;
                *(__nv_bfloat162*)&g_a1lo[(size_t)r * 1024 + col] = pl;
            }
        }
    }
}

// ---------------------------------------------------------------------------
// FC2 via mma.sync bf16x3 (round-10 proven config): h2 = relu(h1@W2+b2)
// CTA: 256 thr, tile M=128 x N=128, K-chunk 32, cp.async 2-stage, ldmatrix.
// grid: (BATCH/128, 8)
// ---------------------------------------------------------------------------
#define TILE_SZ  (128 * ROWB)
#define OFF_AH   0
#define OFF_AL   (1 * TILE_SZ)
#define OFF_BH   (2 * TILE_SZ)
#define OFF_BL   (3 * TILE_SZ)
#define STAGE_SZ (4 * TILE_SZ)
#define FC2_SMEM (2 * STAGE_SZ)

__global__ __launch_bounds__(256) void k_fc2_mma(
    const float* __restrict__ tb2, const float* __restrict__ sb2, int layer)
{
    extern __shared__ char sm[];
    const uint32_t smb = smem_u32(sm);

    const int tid = threadIdx.x;
    const int wid = tid >> 5, lane = tid & 31;
    const int wm = wid >> 1, wn = wid & 1;
    const int qr = lane >> 2, qc = lane & 3;
    const int lr = lane & 7, lg = lane >> 3;

    const int m0 = blockIdx.x * 128;
    const int n0 = blockIdx.y * 128;
    const int hsel = (n0 < HID) ? 0 : HID;

    const __nv_bfloat16* wHi = g_w2hi + (size_t)layer * 1024 * HID;
    const __nv_bfloat16* wLo = g_w2lo + (size_t)layer * 1024 * HID;

    auto load_stage = [&](int st, int kb) {
        const uint32_t base = smb + st * STAGE_SZ;
        #pragma unroll
        for (int t = 0; t < 2; t++) {
            int idx = tid + t * 256;
            int r = idx >> 2, seg = idx & 3;
            uint32_t doff = r * ROWB + seg * 16;
            size_t ga = (size_t)(m0 + r) * 1024 + hsel + kb + seg * 8;
            cp16(base + OFF_AH + doff, g_a1hi + ga);
            cp16(base + OFF_AL + doff, g_a1lo + ga);
            size_t gb = (size_t)(n0 + r) * HID + kb + seg * 8;
            cp16(base + OFF_BH + doff, wHi + gb);
            cp16(base + OFF_BL + doff, wLo + gb);
        }
        CP_COMMIT();
    };

    float acc[2][8][4];
    #pragma unroll
    for (int mf = 0; mf < 2; mf++)
        #pragma unroll
        for (int nf = 0; nf < 8; nf++)
            #pragma unroll
            for (int j = 0; j < 4; j++) acc[mf][nf][j] = 0.0f;

    load_stage(0, 0);

    const uint32_t aOff = (uint32_t)(wm * 32 + lr + (lg & 1) * 8) * ROWB + (lg >> 1) * 16;
    const uint32_t bOff = (uint32_t)(wn * 64 + lr + (lg >> 1) * 8) * ROWB + (lg & 1) * 16;

    for (int ch = 0; ch < 16; ch++) {
        const int st = ch & 1;
        if (ch + 1 < 16) { load_stage(st ^ 1, (ch + 1) * 32); CP_WAIT(1); }
        else             { CP_WAIT(0); }
        __syncthreads();

        const uint32_t tb = smb + st * STAGE_SZ;

        #pragma unroll
        for (int ks = 0; ks < 2; ks++) {
            const uint32_t ko = ks * 32;
            uint32_t Ah[2][4], Al[2][4];
            #pragma unroll
            for (int mf = 0; mf < 2; mf++) {
                uint32_t ra = tb + aOff + mf * 16 * ROWB + ko;
                LDSM_X4(Ah[mf][0], Ah[mf][1], Ah[mf][2], Ah[mf][3], OFF_AH + ra);
                LDSM_X4(Al[mf][0], Al[mf][1], Al[mf][2], Al[mf][3], OFF_AL + ra);
            }
            #pragma unroll
            for (int np = 0; np < 4; np++) {
                uint32_t rb = tb + bOff + np * 16 * ROWB + ko;
                uint32_t Bh[4], Bl[4];
                LDSM_X4(Bh[0], Bh[1], Bh[2], Bh[3], OFF_BH + rb);
                LDSM_X4(Bl[0], Bl[1], Bl[2], Bl[3], OFF_BL + rb);
                #pragma unroll
                for (int h = 0; h < 2; h++)
                    #pragma unroll
                    for (int mf = 0; mf < 2; mf++)
                        mma_bf16(acc[mf][np * 2 + h], Ah[mf], Bh + h * 2);
                #pragma unroll
                for (int h = 0; h < 2; h++)
                    #pragma unroll
                    for (int mf = 0; mf < 2; mf++)
                        mma_bf16(acc[mf][np * 2 + h], Ah[mf], Bl + h * 2);
                #pragma unroll
                for (int h = 0; h < 2; h++)
                    #pragma unroll
                    for (int mf = 0; mf < 2; mf++)
                        mma_bf16(acc[mf][np * 2 + h], Al[mf], Bh + h * 2);
            }
        }
        __syncthreads();
    }

    const float* bias = (n0 < HID) ? tb2 : sb2;
    const int nbase = ((n0 < HID) ? n0 : n0 - HID) + wn * 64;

    #pragma unroll
    for (int mf = 0; mf < 2; mf++) {
        int r0 = m0 + wm * 32 + mf * 16 + qr;
        #pragma unroll
        for (int nf = 0; nf < 8; nf++) {
            int c = nf * 8 + qc * 2;
            float b0 = bias[nbase + c], b1 = bias[nbase + c + 1];
            int col = n0 + wn * 64 + c;
            #pragma unroll
            for (int half = 0; half < 2; half++) {
                int r = r0 + half * 8;
                float v0 = fmaxf(acc[mf][nf][half * 2 + 0] + b0, 0.0f);
                float v1 = fmaxf(acc[mf][nf][half * 2 + 1] + b1, 0.0f);
                __nv_bfloat16 h0, l0, h1, l1;
                split_bf16(v0, h0, l0);
                split_bf16(v1, h1, l1);
                __nv_bfloat162 ph; ph.x = h0; ph.y = h1;
                __nv_bfloat162 pl; pl.x = l0; pl.y = l1;
                *(__nv_bfloat162*)&g_a2hi[(size_t)r * 1024 + col] = ph;
                *(__nv_bfloat162*)&g_a2lo[(size_t)r * 1024 + col] = pl;
            }
        }
    }
}

// ---------------------------------------------------------------------------
// FC3 (dense dual-GEMM, M=64, 3-stage) + coupling epilogue
//   + FUSED FC1 of next layer (z0' = next layer's z1, staged in smem).
// grid: BATCH/64 = 256, 256 thr.
// ---------------------------------------------------------------------------
#define F3_TILE  (64 * ROWB)                   // 5120
#define F3_AHT   0
#define F3_ALT   (1 * F3_TILE)
#define F3_AHS   (2 * F3_TILE)
#define F3_ALS   (3 * F3_TILE)
#define F3_BH    (4 * F3_TILE)
#define F3_BL    (5 * F3_TILE)
#define F3_STAGE (6 * F3_TILE)                 // 30720
#define FC3_SMEM (3 * F3_STAGE)                // 92160
// Fused-FC1 regions (used only after the FC3 mainloop has drained):
#define FZ_HI    20480                         // z1' hi: 64 x ROWB
#define FZ_LO    (20480 + F3_TILE)             // z1' lo
#define FB_BASE  32768                         // 2 B stages of 20480 (BH +0, BL +10240)
#define FB(s)    (FB_BASE + (s) * 20480)

__global__ __launch_bounds__(256, 2) void k_fc3_mma(
    float* __restrict__ out,
    const float* __restrict__ tb3, const float* __restrict__ sb3,
    const float* __restrict__ s_scale, const float* __restrict__ s_shift,
    int layer, int i0off,
    const float* __restrict__ tb1n, const float* __restrict__ sb1n,
    int next_layer)
{
    extern __shared__ char sm[];
    const uint32_t smb = smem_u32(sm);

    const int tid = threadIdx.x;
    const int wid = tid >> 5, lane = tid & 31;
    const int wm = wid >> 1, wn = wid & 1;
    const int qr = lane >> 2, qc = lane & 3;
    const int lr = lane & 7, lg = lane >> 3;

    const int m0 = blockIdx.x * 64;
    const __nv_bfloat16* wHi = g_w3hi + (size_t)layer * 64 * HID;
    const __nv_bfloat16* wLo = g_w3lo + (size_t)layer * 64 * HID;

    const int ldr = tid >> 2, lds = tid & 3;
    auto load_stage = [&](int st, int kb) {
        const uint32_t base = smb + st * F3_STAGE;
        uint32_t doff = ldr * ROWB + lds * 16;
        size_t gt = (size_t)(m0 + ldr) * 1024 + kb + lds * 8;
        cp16(base + F3_AHT + doff, g_a2hi + gt);
        cp16(base + F3_ALT + doff, g_a2lo + gt);
        size_t gs = gt + HID;
        cp16(base + F3_AHS + doff, g_a2hi + gs);
        cp16(base + F3_ALS + doff, g_a2lo + gs);
        size_t gb = (size_t)ldr * HID + kb + lds * 8;
        cp16(base + F3_BH + doff, wHi + gb);
        cp16(base + F3_BL + doff, wLo + gb);
        CP_COMMIT();
    };

    float acc[4][4];
    #pragma unroll
    for (int nf = 0; nf < 4; nf++)
        #pragma unroll
        for (int j = 0; j < 4; j++) acc[nf][j] = 0.0f;

    load_stage(0, 0);
    load_stage(1, 32);
    CP_WAIT(1);
    __syncthreads();

    const uint32_t aSelH = wn ? F3_AHS : F3_AHT;
    const uint32_t aSelL = wn ? F3_ALS : F3_ALT;
    const uint32_t aOff = (uint32_t)(wm * 16 + lr + (lg & 1) * 8) * ROWB + (lg >> 1) * 16;
    const uint32_t bOff = (uint32_t)(wn * 32 + lr + (lg >> 1) * 8) * ROWB + (lg & 1) * 16;

    int st = 0;
    for (int ch = 0; ch < 16; ch++) {
        if (ch + 2 < 16) {
            int st2 = st + 2; if (st2 >= 3) st2 -= 3;
            load_stage(st2, (ch + 2) * 32);
        }

        const uint32_t tb = smb + st * F3_STAGE;

        #pragma unroll
        for (int ks = 0; ks < 2; ks++) {
            const uint32_t ko = ks * 32;
            uint32_t Ah[4], Al[4];
            {
                uint32_t ra = tb + aOff + ko;
                LDSM_X4(Ah[0], Ah[1], Ah[2], Ah[3], aSelH + ra);
                LDSM_X4(Al[0], Al[1], Al[2], Al[3], aSelL + ra);
            }
            #pragma unroll
            for (int np = 0; np < 2; np++) {
                uint32_t rb = tb + bOff + np * 16 * ROWB + ko;
                uint32_t Bh[4], Bl[4];
                LDSM_X4(Bh[0], Bh[1], Bh[2], Bh[3], F3_BH + rb);
                LDSM_X4(Bl[0], Bl[1], Bl[2], Bl[3], F3_BL + rb);
                #pragma unroll
                for (int h = 0; h < 2; h++)
                    mma_bf16(acc[np * 2 + h], Ah, Bh + h * 2);
                #pragma unroll
                for (int h = 0; h < 2; h++)
                    mma_bf16(acc[np * 2 + h], Ah, Bl + h * 2);
                #pragma unroll
                for (int h = 0; h < 2; h++)
                    mma_bf16(acc[np * 2 + h], Al, Bh + h * 2);
            }
        }

        if (ch + 2 < 16)      CP_WAIT(1);
        else if (ch + 1 < 16) CP_WAIT(0);
        __syncthreads();

        if (++st == 3) st = 0;
    }

    // Stage raw t/s to smem: stg[m_local][c], c 0..63 (t from wn=0, s from wn=1)
    float* stg = (float*)sm;
    {
        int rl0 = wm * 16 + qr;
        #pragma unroll
        for (int nf = 0; nf < 4; nf++) {
            int c = wn * 32 + nf * 8 + qc * 2;
            *(float2*)&stg[rl0 * 64 + c]       = *(float2*)&acc[nf][0];
            *(float2*)&stg[(rl0 + 8) * 64 + c] = *(float2*)&acc[nf][2];
        }
    }
    __syncthreads();

    // Prefetch W1(next) chunk 0 while the coupling epilogue runs.
    const __nv_bfloat16* w1h = g_w1hi + (size_t)(next_layer >= 0 ? next_layer : 0) * 1024 * NH;
    const __nv_bfloat16* w1l = g_w1lo + (size_t)(next_layer >= 0 ? next_layer : 0) * 1024 * NH;
    auto load_b1 = [&](int s, int n0b) {
        const uint32_t base = smb + FB(s);
        #pragma unroll
        for (int t = 0; t < 2; t++) {
            int idx = tid + t * 256;
            int r = idx >> 2, seg = idx & 3;
            uint32_t doff = r * ROWB + seg * 16;
            size_t gb = (size_t)(n0b + r) * NH + seg * 8;
            cp16(base + doff, w1h + gb);
            cp16(base + 10240 + doff, w1l + gb);
        }
        CP_COMMIT();
    };
    if (next_layer >= 0) load_b1(0, 0);

    // Coupling epilogue: 64 rows x 32 cols = 2048 elems, 8 per thread.
    // Also stage z0' (= next layer's z1) into FZ split hi/lo.
    #pragma unroll
    for (int q = 0; q < 8; q++) {
        int idx = tid + q * 256;
        int rl = idx >> 5, c = idx & 31;
        int m = m0 + rl;
        float tval = stg[rl * 64 + c] + tb3[c];
        float sraw = stg[rl * 64 + 32 + c] + sb3[c];
        float s = tanhf(sraw) * s_scale[c] + s_shift[c];
        int zi = m * NDIMS + 2 * c + i0off;
        float z0 = out[zi];
        float znew = z0 * expf(s) + tval;
        out[zi] = znew;
        out[BATCH * NDIMS + zi] += s;
        if (next_layer >= 0) {
            __nv_bfloat16 hi, lo;
            split_bf16(znew, hi, lo);
            *(__nv_bfloat16*)(sm + FZ_HI + rl * ROWB + c * 2) = hi;
            *(__nv_bfloat16*)(sm + FZ_LO + rl * ROWB + c * 2) = lo;
        }
    }

    if (next_layer < 0) return;

    // ---- Fused FC1 of next layer: h1 = relu(z1' @ W1n + b1n) ----
    load_b1(1, 128);
    __syncthreads();     // FZ visible to all; B0 cp.async groups committed

    // warp grid for FC1: 2(M) x 4(N), warp tile 32x32 per 128-wide N chunk
    const int wm1 = wid >> 2, wn1 = wid & 3;
    const uint32_t aOff1 = (uint32_t)(wm1 * 32 + lr + (lg & 1) * 8) * ROWB + (lg >> 1) * 16;
    const uint32_t bOff1 = (uint32_t)(wn1 * 32 + lr + (lg >> 1) * 8) * ROWB + (lg & 1) * 16;

    // A fragments (z1'): load once, reused for all 8 N-chunks
    uint32_t A1h[2][2][4], A1l[2][2][4];     // [ks][mf]
    CP_WAIT(1);                               // B0 arrived (B1 may pend)
    __syncthreads();
    #pragma unroll
    for (int ks = 0; ks < 2; ks++)
        #pragma unroll
        for (int mf = 0; mf < 2; mf++) {
            uint32_t ra = smb + aOff1 + mf * 16 * ROWB + ks * 32;
            LDSM_X4(A1h[ks][mf][0], A1h[ks][mf][1], A1h[ks][mf][2], A1h[ks][mf][3], FZ_HI + ra);
            LDSM_X4(A1l[ks][mf][0], A1l[ks][mf][1], A1l[ks][mf][2], A1l[ks][mf][3], FZ_LO + ra);
        }

    for (int nb = 0; nb < 8; nb++) {
        if (nb > 0) {
            if (nb < 7) { CP_WAIT(1); }
            else        { CP_WAIT(0); }
            __syncthreads();
        }
        const uint32_t bbase = smb + FB(nb & 1);

        float a1[2][4][4];
        #pragma unroll
        for (int mf = 0; mf < 2; mf++)
            #pragma unroll
            for (int nf = 0; nf < 4; nf++)
                #pragma unroll
                for (int j = 0; j < 4; j++) a1[mf][nf][j] = 0.0f;

        #pragma unroll
        for (int ks = 0; ks < 2; ks++) {
            const uint32_t ko = ks * 32;
            #pragma unroll
            for (int np = 0; np < 2; np++) {
                uint32_t rb = bbase + bOff1 + np * 16 * ROWB + ko;
                uint32_t Bh[4], Bl[4];
                LDSM_X4(Bh[0], Bh[1], Bh[2], Bh[3], rb);
                LDSM_X4(Bl[0], Bl[1], Bl[2], Bl[3], rb + 10240);
                #pragma unroll
                for (int h = 0; h < 2; h++)
                    #pragma unroll
                    for (int mf = 0; mf < 2; mf++)
                        mma_bf16(a1[mf][np * 2 + h], A1h[ks][mf], Bh + h * 2);
                #pragma unroll
                for (int h = 0; h < 2; h++)
                    #pragma unroll
                    for (int mf = 0; mf < 2; mf++)
                        mma_bf16(a1[mf][np * 2 + h], A1h[ks][mf], Bl + h * 2);
                #pragma unroll
                for (int h = 0; h < 2; h++)
                    #pragma unroll
                    for (int mf = 0; mf < 2; mf++)
                        mma_bf16(a1[mf][np * 2 + h], A1l[ks][mf], Bh + h * 2);
            }
        }
        __syncthreads();      // everyone done reading stage nb&1
        if (nb + 2 < 8) load_b1(nb & 1, (nb + 2) * 128);

        // Epilogue for this N-chunk -> g_a1 (bit-identical to standalone FC1)
        const int n0c = nb * 128;
        const float* bias = (n0c < HID) ? tb1n : sb1n;
        const int nbase = ((n0c < HID) ? n0c : n0c - HID) + wn1 * 32;
        #pragma unroll
        for (int mf = 0; mf < 2; mf++) {
            int r0 = m0 + wm1 * 32 + mf * 16 + qr;
            #pragma unroll
            for (int nf = 0; nf < 4; nf++) {
                int c = nf * 8 + qc * 2;
                float b0 = bias[nbase + c], b1 = bias[nbase + c + 1];
                int col = n0c + wn1 * 32 + c;
                #pragma unroll
                for (int half = 0; half < 2; half++) {
                    int r = r0 + half * 8;
                    float v0 = fmaxf(a1[mf][nf][half * 2 + 0] + b0, 0.0f);
                    float v1 = fmaxf(a1[mf][nf][half * 2 + 1] + b1, 0.0f);
                    __nv_bfloat16 h0, l0, h1, l1;
                    split_bf16(v0, h0, l0);
                    split_bf16(v1, h1, l1);
                    __nv_bfloat162 ph; ph.x = h0; ph.y = h1;
                    __nv_bfloat162 pl; pl.x = l0; pl.y = l1;
                    *(__nv_bfloat162*)&g_a1hi[(size_t)r * 1024 + col] = ph;
                    *(__nv_bfloat162*)&g_a1lo[(size_t)r * 1024 + col] = pl;
                }
            }
        }
    }
}

// ---------------------------------------------------------------------------
// Launch
// ---------------------------------------------------------------------------
extern "C" void kernel_launch(void* const* d_in, const int* in_sizes, int n_in,
                              void* d_out, int out_size) {
    const float* y       = (const float*)d_in[0];
    const float* tW1     = (const float*)d_in[1];
    const float* tb1     = (const float*)d_in[2];
    const float* tW2     = (const float*)d_in[3];
    const float* tb2     = (const float*)d_in[4];
    const float* tW3     = (const float*)d_in[5];
    const float* tb3     = (const float*)d_in[6];
    const float* sW1     = (const float*)d_in[7];
    const float* sb1     = (const float*)d_in[8];
    const float* sW2     = (const float*)d_in[9];
    const float* sb2     = (const float*)d_in[10];
    const float* sW3     = (const float*)d_in[11];
    const float* sb3     = (const float*)d_in[12];
    const float* s_scale = (const float*)d_in[13];
    const float* s_shift = (const float*)d_in[14];
    float* out = (float*)d_out;

    cudaFuncSetAttribute(k_fc2_mma, cudaFuncAttributeMaxDynamicSharedMemorySize, FC2_SMEM);
    cudaFuncSetAttribute(k_fc3_mma, cudaFuncAttributeMaxDynamicSharedMemorySize, FC3_SMEM);

    k_init<<<(BATCH * NDIMS + 255) / 256, 256>>>(y, out);
    k_split_w1<<<(NL * 1024 * NH + 255) / 256, 256>>>(tW1, sW1);
    k_split_w2<<<(NL * 1024 * HID + 255) / 256, 256>>>(tW2, sW2);
    k_split_w3<<<(NL * 64 * HID + 255) / 256, 256>>>(tW3, sW3);

    const dim3 g1(BATCH / 128, 1024 / 128);
    const dim3 g2(BATCH / 128, 1024 / 128);

    // Layer 0 FC1 reads y directly (same values as z at that point).
    k_fc1_mma<<<g1, 256>>>(y, tb1, sb1, 0, /*i1off layer0*/ 1);

    for (int i = 0; i < NL; i++) {
        const int p = i & 1;
        const int i0off = p ? 1 : 0;
        const int nxt = (i + 1 < NL) ? (i + 1) : -1;

        k_fc2_mma<<<g2, 256, FC2_SMEM>>>(tb2 + (size_t)i * HID, sb2 + (size_t)i * HID, i);
        k_fc3_mma<<<BATCH / 64, 256, FC3_SMEM>>>(
            out, tb3 + (size_t)i * NH, sb3 + (size_t)i * NH,
            s_scale + (size_t)i * NH, s_shift + (size_t)i * NH, i, i0off,
            tb1 + (size_t)(nxt >= 0 ? nxt : 0) * HID,
            sb1 + (size_t)(nxt >= 0 ? nxt : 0) * HID,
            nxt);
    }
}

// round 13
// speedup vs baseline: 1.3559x; 1.3559x over previous
#include <cuda_runtime.h>
#include <cuda_bf16.h>
#include <cstdint>
#include <math.h>

#define BATCH 16384
#define NDIMS 64
#define NH 32
#define HID 512
#define NL 8

// ---------------------------------------------------------------------------
// Scratch (device globals; no allocations allowed)
// ---------------------------------------------------------------------------
__device__ __nv_bfloat16 g_a1hi[BATCH * 1024];      // h1 split hi  [m][1024]
__device__ __nv_bfloat16 g_a1lo[BATCH * 1024];
__device__ __nv_bfloat16 g_a2hi[BATCH * 1024];      // h2 split hi  [m][1024]
__device__ __nv_bfloat16 g_a2lo[BATCH * 1024];
__device__ __nv_bfloat16 g_w1hi[NL * 1024 * NH];    // W1^T split [l][n][k=32]
__device__ __nv_bfloat16 g_w1lo[NL * 1024 * NH];
__device__ __nv_bfloat16 g_w2hi[NL * 1024 * HID];   // W2^T split [l][n][k=512]
__device__ __nv_bfloat16 g_w2lo[NL * 1024 * HID];
__device__ __nv_bfloat16 g_w3hi[NL * 64 * HID];     // W3 dense [l][n=64][k=512]
__device__ __nv_bfloat16 g_w3lo[NL * 64 * HID];     //  rows 0-31: tW3^T, 32-63: sW3^T

// ---------------------------------------------------------------------------
// PTX helpers (sm_80-level features only: cp.async + mma.sync + ldmatrix)
// ---------------------------------------------------------------------------
__device__ __forceinline__ uint32_t smem_u32(const void* p) {
    uint32_t a;
    asm("{ .reg .u64 t; cvta.to.shared.u64 t, %1; cvt.u32.u64 %0, t; }" : "=r"(a) : "l"(p));
    return a;
}
__device__ __forceinline__ void cp16(uint32_t dst, const void* src) {
    asm volatile("cp.async.cg.shared.global [%0], [%1], 16;" :: "r"(dst), "l"(src));
}
#define CP_COMMIT() asm volatile("cp.async.commit_group;" ::: "memory")
#define CP_WAIT(n)  asm volatile("cp.async.wait_group %0;" :: "n"(n) : "memory")

// non-volatile: register-only op, lets ptxas schedule/interleave MMAs.
__device__ __forceinline__ void mma_bf16(float* d, const uint32_t* a, const uint32_t* b) {
    asm("mma.sync.aligned.m16n8k16.row.col.f32.bf16.bf16.f32 "
        "{%0,%1,%2,%3}, {%4,%5,%6,%7}, {%8,%9}, {%0,%1,%2,%3};"
        : "+f"(d[0]), "+f"(d[1]), "+f"(d[2]), "+f"(d[3])
        : "r"(a[0]), "r"(a[1]), "r"(a[2]), "r"(a[3]), "r"(b[0]), "r"(b[1]));
}
#define LDSM_X4(r0, r1, r2, r3, addr)                                          \
    asm volatile("ldmatrix.sync.aligned.m8n8.x4.shared.b16 {%0,%1,%2,%3}, [%4];" \
        : "=r"(r0), "=r"(r1), "=r"(r2), "=r"(r3) : "r"(addr))

__device__ __forceinline__ void split_bf16(float v, __nv_bfloat16& hi, __nv_bfloat16& lo) {
    hi = __float2bfloat16(v);
    lo = __float2bfloat16(v - __bfloat162float(hi));
}

#define ROWB 80                     // padded row stride (FC1/FC3 tiles)

// ---------------------------------------------------------------------------
// Init: z = y, log_det = 0
// ---------------------------------------------------------------------------
__global__ void k_init(const float* __restrict__ y, float* __restrict__ out) {
    int i = blockIdx.x * blockDim.x + threadIdx.x;
    if (i < BATCH * NDIMS) {
        out[i] = y[i];
        out[BATCH * NDIMS + i] = 0.0f;
    }
}

// ---------------------------------------------------------------------------
// Weight pre-splits
// ---------------------------------------------------------------------------
__global__ __launch_bounds__(256) void k_split_w1(const float* __restrict__ tW1,
                                                  const float* __restrict__ sW1) {
    int i = blockIdx.x * 256 + threadIdx.x;
    if (i >= NL * 1024 * NH) return;
    int l = i / (1024 * NH);
    int rem = i - l * 1024 * NH;
    int n = rem / NH;
    int k = rem - n * NH;
    const float* W = (n < HID) ? tW1 : sW1;
    int nn = (n < HID) ? n : n - HID;
    float v = W[(size_t)l * NH * HID + k * HID + nn];
    split_bf16(v, g_w1hi[i], g_w1lo[i]);
}

__global__ __launch_bounds__(256) void k_split_w2(const float* __restrict__ tW2,
                                                  const float* __restrict__ sW2) {
    int i = blockIdx.x * 256 + threadIdx.x;
    if (i >= NL * 1024 * HID) return;
    int l = i / (1024 * HID);
    int rem = i - l * 1024 * HID;
    int n = rem / HID;
    int k = rem - n * HID;
    const float* W = (n < HID) ? tW2 : sW2;
    int nn = (n < HID) ? n : n - HID;
    float v = W[(size_t)l * HID * HID + k * HID + nn];
    split_bf16(v, g_w2hi[i], g_w2lo[i]);
}

// W3 dense: [l][n=64][k=512]; n<32 -> tW3[k][n], n>=32 -> sW3[k][n-32]
__global__ __launch_bounds__(256) void k_split_w3(const float* __restrict__ tW3,
                                                  const float* __restrict__ sW3) {
    int i = blockIdx.x * 256 + threadIdx.x;
    if (i >= NL * 64 * HID) return;
    int l = i / (64 * HID);
    int rem = i - l * 64 * HID;
    int n = rem / HID;
    int k = rem - n * HID;
    float v = (n < NH) ? tW3[(size_t)l * HID * NH + k * NH + n]
                       : sW3[(size_t)l * HID * NH + k * NH + (n - NH)];
    __nv_bfloat16 hi, lo;
    split_bf16(v, hi, lo);
    g_w3hi[i] = hi;
    g_w3lo[i] = lo;
}

// ---------------------------------------------------------------------------
// FC1 via mma.sync bf16x3: h1 = relu(z1 @ W1 + b1) -> bf16 hi/lo
// CTA: 256 thr, tile M=128 x N=128, K=32 single-shot. grid: (BATCH/128, 8)
// ---------------------------------------------------------------------------
__global__ __launch_bounds__(256) void k_fc1_mma(
    const float* __restrict__ zbuf,
    const float* __restrict__ tb1, const float* __restrict__ sb1,
    int layer, int i1off)
{
    __shared__ __align__(16) char sAh[128 * ROWB];
    __shared__ __align__(16) char sAl[128 * ROWB];
    __shared__ __align__(16) char sBh[128 * ROWB];
    __shared__ __align__(16) char sBl[128 * ROWB];

    const int tid = threadIdx.x;
    const int wid = tid >> 5, lane = tid & 31;
    const int wm = wid >> 1, wn = wid & 1;
    const int qr = lane >> 2, qc = lane & 3;
    const int lr = lane & 7, lg = lane >> 3;

    const int m0 = blockIdx.x * 128;
    const int n0 = blockIdx.y * 128;

    for (int idx = tid; idx < 128 * 32; idx += 256) {
        int r = idx >> 5, k = idx & 31;
        float v = zbuf[(m0 + r) * NDIMS + 2 * k + i1off];
        __nv_bfloat16 hi, lo;
        split_bf16(v, hi, lo);
        *(__nv_bfloat16*)(sAh + r * ROWB + k * 2) = hi;
        *(__nv_bfloat16*)(sAl + r * ROWB + k * 2) = lo;
    }
    {
        const __nv_bfloat16* bh = g_w1hi + ((size_t)layer * 1024 + n0) * NH;
        const __nv_bfloat16* bl = g_w1lo + ((size_t)layer * 1024 + n0) * NH;
        for (int idx = tid; idx < 128 * 4; idx += 256) {
            int r = idx >> 2, seg = idx & 3;
            *(uint4*)(sBh + r * ROWB + seg * 16) = *(const uint4*)(bh + r * NH + seg * 8);
            *(uint4*)(sBl + r * ROWB + seg * 16) = *(const uint4*)(bl + r * NH + seg * 8);
        }
    }
    __syncthreads();

    const uint32_t ah = smem_u32(sAh), al = smem_u32(sAl);
    const uint32_t bh = smem_u32(sBh), bl = smem_u32(sBl);
    const uint32_t aOff = (uint32_t)(wm * 32 + lr + (lg & 1) * 8) * ROWB + (lg >> 1) * 16;
    const uint32_t bOff = (uint32_t)(wn * 64 + lr + (lg >> 1) * 8) * ROWB + (lg & 1) * 16;

    float acc[2][8][4];
    #pragma unroll
    for (int mf = 0; mf < 2; mf++)
        #pragma unroll
        for (int nf = 0; nf < 8; nf++)
            #pragma unroll
            for (int j = 0; j < 4; j++) acc[mf][nf][j] = 0.0f;

    #pragma unroll
    for (int ks = 0; ks < 2; ks++) {
        const uint32_t ko = ks * 32;
        uint32_t Ah[2][4], Al[2][4];
        #pragma unroll
        for (int mf = 0; mf < 2; mf++) {
            uint32_t ra = aOff + mf * 16 * ROWB + ko;
            LDSM_X4(Ah[mf][0], Ah[mf][1], Ah[mf][2], Ah[mf][3], ah + ra);
            LDSM_X4(Al[mf][0], Al[mf][1], Al[mf][2], Al[mf][3], al + ra);
        }
        #pragma unroll
        for (int np = 0; np < 4; np++) {
            uint32_t rb = bOff + np * 16 * ROWB + ko;
            uint32_t Bh[4], Bl[4];
            LDSM_X4(Bh[0], Bh[1], Bh[2], Bh[3], bh + rb);
            LDSM_X4(Bl[0], Bl[1], Bl[2], Bl[3], bl + rb);
            #pragma unroll
            for (int h = 0; h < 2; h++)
                #pragma unroll
                for (int mf = 0; mf < 2; mf++)
                    mma_bf16(acc[mf][np * 2 + h], Ah[mf], Bh + h * 2);
            #pragma unroll
            for (int h = 0; h < 2; h++)
                #pragma unroll
                for (int mf = 0; mf < 2; mf++)
                    mma_bf16(acc[mf][np * 2 + h], Ah[mf], Bl + h * 2);
            #pragma unroll
            for (int h = 0; h < 2; h++)
                #pragma unroll
                for (int mf = 0; mf < 2; mf++)
                    mma_bf16(acc[mf][np * 2 + h], Al[mf], Bh + h * 2);
        }
    }

    const float* bias = (n0 < HID) ? tb1 : sb1;
    const int nbase = ((n0 < HID) ? n0 : n0 - HID) + wn * 64;

    #pragma unroll
    for (int mf = 0; mf < 2; mf++) {
        int r0 = m0 + wm * 32 + mf * 16 + qr;
        #pragma unroll
        for (int nf = 0; nf < 8; nf++) {
            int c = nf * 8 + qc * 2;
            float b0 = bias[nbase + c], b1 = bias[nbase + c + 1];
            int col = n0 + wn * 64 + c;
            #pragma unroll
            for (int half = 0; half < 2; half++) {
                int r = r0 + half * 8;
                float v0 = fmaxf(acc[mf][nf][half * 2 + 0] + b0, 0.0f);
                float v1 = fmaxf(acc[mf][nf][half * 2 + 1] + b1, 0.0f);
                __nv_bfloat16 h0, l0, h1, l1;
                split_bf16(v0, h0, l0);
                split_bf16(v1, h1, l1);
                __nv_bfloat162 ph; ph.x = h0; ph.y = h1;
                __nv_bfloat162 pl; pl.x = l0; pl.y = l1;
                *(__nv_bfloat162*)&g_a1hi[(size_t)r * 1024 + col] = ph;
                *(__nv_bfloat162*)&g_a1lo[(size_t)r * 1024 + col] = pl;
            }
        }
    }
}

// ---------------------------------------------------------------------------
// FC2 via mma.sync bf16x3: h2 = relu(h1 @ W2 + b2) -> bf16 hi/lo
// CTA: 256 thr, tile M=128 x N=128, K-chunk 32.
// SWIZZLED smem (64B rows, addr = r*64 + ((seg ^ ((r>>1)&3))*16)) -> stage
// 32 KB; 3-stage single-barrier cp.async pipeline; 2 CTAs/SM retained.
// grid: (BATCH/128, 8)
// ---------------------------------------------------------------------------
#define F2_TILE  (128 * 64)                    // 8192
#define OFF_AH   0
#define OFF_AL   (1 * F2_TILE)
#define OFF_BH   (2 * F2_TILE)
#define OFF_BL   (3 * F2_TILE)
#define STAGE_SZ (4 * F2_TILE)                 // 32768
#define FC2_SMEM (3 * STAGE_SZ)                // 98304

__global__ __launch_bounds__(256) void k_fc2_mma(
    const float* __restrict__ tb2, const float* __restrict__ sb2, int layer)
{
    extern __shared__ char sm[];
    const uint32_t smb = smem_u32(sm);

    const int tid = threadIdx.x;
    const int wid = tid >> 5, lane = tid & 31;
    const int wm = wid >> 1, wn = wid & 1;
    const int qr = lane >> 2, qc = lane & 3;
    const int lr = lane & 7, lg = lane >> 3;

    const int m0 = blockIdx.x * 128;
    const int n0 = blockIdx.y * 128;
    const int hsel = (n0 < HID) ? 0 : HID;

    const __nv_bfloat16* wHi = g_w2hi + (size_t)layer * 1024 * HID;
    const __nv_bfloat16* wLo = g_w2lo + (size_t)layer * 1024 * HID;

    auto load_stage = [&](int st, int kb) {
        const uint32_t base = smb + st * STAGE_SZ;
        #pragma unroll
        for (int t = 0; t < 2; t++) {
            int idx = tid + t * 256;
            int r = idx >> 2, seg = idx & 3;
            uint32_t doff = (uint32_t)r * 64 + (uint32_t)((seg ^ ((r >> 1) & 3)) * 16);
            size_t ga = (size_t)(m0 + r) * 1024 + hsel + kb + seg * 8;
            cp16(base + OFF_AH + doff, g_a1hi + ga);
            cp16(base + OFF_AL + doff, g_a1lo + ga);
            size_t gb = (size_t)(n0 + r) * HID + kb + seg * 8;
            cp16(base + OFF_BH + doff, wHi + gb);
            cp16(base + OFF_BL + doff, wLo + gb);
        }
        CP_COMMIT();
    };

    float acc[2][8][4];
    #pragma unroll
    for (int mf = 0; mf < 2; mf++)
        #pragma unroll
        for (int nf = 0; nf < 8; nf++)
            #pragma unroll
            for (int j = 0; j < 4; j++) acc[mf][nf][j] = 0.0f;

    load_stage(0, 0);
    load_stage(1, 32);
    CP_WAIT(1);
    __syncthreads();

    // per-lane swizzle selector: all ldmatrix row bases are multiples of 8,
    // so ((row>>1)&3) == ((lr>>1)&3) for every matrix this lane touches.
    const uint32_t swz = (uint32_t)((lr >> 1) & 3);
    const uint32_t aRowB = (uint32_t)(wm * 32 + lr + (lg & 1) * 8) * 64;
    const uint32_t aSegB = (uint32_t)(lg >> 1);
    const uint32_t bRowB = (uint32_t)(wn * 64 + lr + (lg >> 1) * 8) * 64;
    const uint32_t bSegB = (uint32_t)(lg & 1);

    int st = 0;
    for (int ch = 0; ch < 16; ch++) {
        if (ch + 2 < 16) {
            int st2 = st + 2; if (st2 >= 3) st2 -= 3;
            load_stage(st2, (ch + 2) * 32);
        }

        const uint32_t tb = smb + st * STAGE_SZ;

        #pragma unroll
        for (int ks = 0; ks < 2; ks++) {
            const uint32_t aCol = ((ks * 2 + aSegB) ^ swz) * 16;
            const uint32_t bCol = ((ks * 2 + bSegB) ^ swz) * 16;
            uint32_t Ah[2][4], Al[2][4];
            #pragma unroll
            for (int mf = 0; mf < 2; mf++) {
                uint32_t ra = tb + aRowB + mf * 16 * 64 + aCol;
                LDSM_X4(Ah[mf][0], Ah[mf][1], Ah[mf][2], Ah[mf][3], OFF_AH + ra);
                LDSM_X4(Al[mf][0], Al[mf][1], Al[mf][2], Al[mf][3], OFF_AL + ra);
            }
            #pragma unroll
            for (int np = 0; np < 4; np++) {
                uint32_t rb = tb + bRowB + np * 16 * 64 + bCol;
                uint32_t Bh[4], Bl[4];
                LDSM_X4(Bh[0], Bh[1], Bh[2], Bh[3], OFF_BH + rb);
                LDSM_X4(Bl[0], Bl[1], Bl[2], Bl[3], OFF_BL + rb);
                #pragma unroll
                for (int h = 0; h < 2; h++)
                    #pragma unroll
                    for (int mf = 0; mf < 2; mf++)
                        mma_bf16(acc[mf][np * 2 + h], Ah[mf], Bh + h * 2);
                #pragma unroll
                for (int h = 0; h < 2; h++)
                    #pragma unroll
                    for (int mf = 0; mf < 2; mf++)
                        mma_bf16(acc[mf][np * 2 + h], Ah[mf], Bl + h * 2);
                #pragma unroll
                for (int h = 0; h < 2; h++)
                    #pragma unroll
                    for (int mf = 0; mf < 2; mf++)
                        mma_bf16(acc[mf][np * 2 + h], Al[mf], Bh + h * 2);
            }
        }

        if (ch + 2 < 16)      CP_WAIT(1);
        else if (ch + 1 < 16) CP_WAIT(0);
        __syncthreads();

        if (++st == 3) st = 0;
    }

    const float* bias = (n0 < HID) ? tb2 : sb2;
    const int nbase = ((n0 < HID) ? n0 : n0 - HID) + wn * 64;

    #pragma unroll
    for (int mf = 0; mf < 2; mf++) {
        int r0 = m0 + wm * 32 + mf * 16 + qr;
        #pragma unroll
        for (int nf = 0; nf < 8; nf++) {
            int c = nf * 8 + qc * 2;
            float b0 = bias[nbase + c], b1 = bias[nbase + c + 1];
            int col = n0 + wn * 64 + c;
            #pragma unroll
            for (int half = 0; half < 2; half++) {
                int r = r0 + half * 8;
                float v0 = fmaxf(acc[mf][nf][half * 2 + 0] + b0, 0.0f);
                float v1 = fmaxf(acc[mf][nf][half * 2 + 1] + b1, 0.0f);
                __nv_bfloat16 h0, l0, h1, l1;
                split_bf16(v0, h0, l0);
                split_bf16(v1, h1, l1);
                __nv_bfloat162 ph; ph.x = h0; ph.y = h1;
                __nv_bfloat162 pl; pl.x = l0; pl.y = l1;
                *(__nv_bfloat162*)&g_a2hi[(size_t)r * 1024 + col] = ph;
                *(__nv_bfloat162*)&g_a2lo[(size_t)r * 1024 + col] = pl;
            }
        }
    }
}

// ---------------------------------------------------------------------------
// FC3 via mma.sync bf16x3 + coupling epilogue. DENSE dual-GEMM, M=64 tiles:
//   wn=0 warps: t = h2[:, 0:512)   @ tW3   (B rows 0-31)
//   wn=1 warps: s = h2[:, 512:1024) @ sW3  (B rows 32-63)
// CTA: 256 thr (warp grid 4(M) x 2(N), warp tile 16x32), 16 K-chunks of 32,
// cp.async 3-stage single-barrier pipeline, ldmatrix. grid: BATCH/64 = 256.
// ---------------------------------------------------------------------------
#define F3_TILE  (64 * ROWB)                   // 5120
#define F3_AHT   0
#define F3_ALT   (1 * F3_TILE)
#define F3_AHS   (2 * F3_TILE)
#define F3_ALS   (3 * F3_TILE)
#define F3_BH    (4 * F3_TILE)
#define F3_BL    (5 * F3_TILE)
#define F3_STAGE (6 * F3_TILE)                 // 30720
#define FC3_SMEM (3 * F3_STAGE)                // 92160

__global__ __launch_bounds__(256) void k_fc3_mma(
    float* __restrict__ out,
    const float* __restrict__ tb3, const float* __restrict__ sb3,
    const float* __restrict__ s_scale, const float* __restrict__ s_shift,
    int layer, int i0off)
{
    extern __shared__ char sm[];
    const uint32_t smb = smem_u32(sm);

    const int tid = threadIdx.x;
    const int wid = tid >> 5, lane = tid & 31;
    const int wm = wid >> 1, wn = wid & 1;
    const int qr = lane >> 2, qc = lane & 3;
    const int lr = lane & 7, lg = lane >> 3;

    const int m0 = blockIdx.x * 64;
    const __nv_bfloat16* wHi = g_w3hi + (size_t)layer * 64 * HID;
    const __nv_bfloat16* wLo = g_w3lo + (size_t)layer * 64 * HID;

    const int ldr = tid >> 2, lds = tid & 3;
    auto load_stage = [&](int st, int kb) {
        const uint32_t base = smb + st * F3_STAGE;
        uint32_t doff = ldr * ROWB + lds * 16;
        size_t gt = (size_t)(m0 + ldr) * 1024 + kb + lds * 8;
        cp16(base + F3_AHT + doff, g_a2hi + gt);
        cp16(base + F3_ALT + doff, g_a2lo + gt);
        size_t gs = gt + HID;
        cp16(base + F3_AHS + doff, g_a2hi + gs);
        cp16(base + F3_ALS + doff, g_a2lo + gs);
        size_t gb = (size_t)ldr * HID + kb + lds * 8;
        cp16(base + F3_BH + doff, wHi + gb);
        cp16(base + F3_BL + doff, wLo + gb);
        CP_COMMIT();
    };

    float acc[4][4];
    #pragma unroll
    for (int nf = 0; nf < 4; nf++)
        #pragma unroll
        for (int j = 0; j < 4; j++) acc[nf][j] = 0.0f;

    load_stage(0, 0);
    load_stage(1, 32);
    CP_WAIT(1);
    __syncthreads();

    const uint32_t aSelH = wn ? F3_AHS : F3_AHT;
    const uint32_t aSelL = wn ? F3_ALS : F3_ALT;
    const uint32_t aOff = (uint32_t)(wm * 16 + lr + (lg & 1) * 8) * ROWB + (lg >> 1) * 16;
    const uint32_t bOff = (uint32_t)(wn * 32 + lr + (lg >> 1) * 8) * ROWB + (lg & 1) * 16;

    int st = 0;
    for (int ch = 0; ch < 16; ch++) {
        if (ch + 2 < 16) {
            int st2 = st + 2; if (st2 >= 3) st2 -= 3;
            load_stage(st2, (ch + 2) * 32);
        }

        const uint32_t tb = smb + st * F3_STAGE;

        #pragma unroll
        for (int ks = 0; ks < 2; ks++) {
            const uint32_t ko = ks * 32;
            uint32_t Ah[4], Al[4];
            {
                uint32_t ra = tb + aOff + ko;
                LDSM_X4(Ah[0], Ah[1], Ah[2], Ah[3], aSelH + ra);
                LDSM_X4(Al[0], Al[1], Al[2], Al[3], aSelL + ra);
            }
            #pragma unroll
            for (int np = 0; np < 2; np++) {
                uint32_t rb = tb + bOff + np * 16 * ROWB + ko;
                uint32_t Bh[4], Bl[4];
                LDSM_X4(Bh[0], Bh[1], Bh[2], Bh[3], F3_BH + rb);
                LDSM_X4(Bl[0], Bl[1], Bl[2], Bl[3], F3_BL + rb);
                #pragma unroll
                for (int h = 0; h < 2; h++)
                    mma_bf16(acc[np * 2 + h], Ah, Bh + h * 2);
                #pragma unroll
                for (int h = 0; h < 2; h++)
                    mma_bf16(acc[np * 2 + h], Ah, Bl + h * 2);
                #pragma unroll
                for (int h = 0; h < 2; h++)
                    mma_bf16(acc[np * 2 + h], Al, Bh + h * 2);
            }
        }

        if (ch + 2 < 16)      CP_WAIT(1);
        else if (ch + 1 < 16) CP_WAIT(0);
        __syncthreads();

        if (++st == 3) st = 0;
    }

    // Stage raw t/s to smem: stg[m_local][c], c 0..63 (t from wn=0, s from wn=1)
    float* stg = (float*)sm;
    {
        int rl0 = wm * 16 + qr;
        #pragma unroll
        for (int nf = 0; nf < 4; nf++) {
            int c = wn * 32 + nf * 8 + qc * 2;
            *(float2*)&stg[rl0 * 64 + c]       = *(float2*)&acc[nf][0];
            *(float2*)&stg[(rl0 + 8) * 64 + c] = *(float2*)&acc[nf][2];
        }
    }
    __syncthreads();

    // Coupling epilogue: 64 rows x 32 cols = 2048 elems, 8 per thread
    #pragma unroll
    for (int q = 0; q < 8; q++) {
        int idx = tid + q * 256;
        int rl = idx >> 5, c = idx & 31;
        int m = m0 + rl;
        float tval = stg[rl * 64 + c] + tb3[c];
        float sraw = stg[rl * 64 + 32 + c] + sb3[c];
        float s = tanhf(sraw) * s_scale[c] + s_shift[c];
        int zi = m * NDIMS + 2 * c + i0off;
        float z0 = out[zi];
        out[zi] = z0 * expf(s) + tval;
        out[BATCH * NDIMS + zi] += s;
    }
}

// ---------------------------------------------------------------------------
// Launch
// ---------------------------------------------------------------------------
extern "C" void kernel_launch(void* const* d_in, const int* in_sizes, int n_in,
                              void* d_out, int out_size) {
    const float* y       = (const float*)d_in[0];
    const float* tW1     = (const float*)d_in[1];
    const float* tb1     = (const float*)d_in[2];
    const float* tW2     = (const float*)d_in[3];
    const float* tb2     = (const float*)d_in[4];
    const float* tW3     = (const float*)d_in[5];
    const float* tb3     = (const float*)d_in[6];
    const float* sW1     = (const float*)d_in[7];
    const float* sb1     = (const float*)d_in[8];
    const float* sW2     = (const float*)d_in[9];
    const float* sb2     = (const float*)d_in[10];
    const float* sW3     = (const float*)d_in[11];
    const float* sb3     = (const float*)d_in[12];
    const float* s_scale = (const float*)d_in[13];
    const float* s_shift = (const float*)d_in[14];
    float* out = (float*)d_out;

    cudaFuncSetAttribute(k_fc2_mma, cudaFuncAttributeMaxDynamicSharedMemorySize, FC2_SMEM);
    cudaFuncSetAttribute(k_fc3_mma, cudaFuncAttributeMaxDynamicSharedMemorySize, FC3_SMEM);

    k_init<<<(BATCH * NDIMS + 255) / 256, 256>>>(y, out);
    k_split_w1<<<(NL * 1024 * NH + 255) / 256, 256>>>(tW1, sW1);
    k_split_w2<<<(NL * 1024 * HID + 255) / 256, 256>>>(tW2, sW2);
    k_split_w3<<<(NL * 64 * HID + 255) / 256, 256>>>(tW3, sW3);

    const dim3 g1(BATCH / 128, 1024 / 128);
    const dim3 g2(BATCH / 128, 1024 / 128);

    for (int i = 0; i < NL; i++) {
        const int p = i & 1;
        const int i0off = p ? 1 : 0;
        const int i1off = p ? 0 : 1;

        k_fc1_mma<<<g1, 256>>>(out, tb1 + (size_t)i * HID, sb1 + (size_t)i * HID, i, i1off);
        k_fc2_mma<<<g2, 256, FC2_SMEM>>>(tb2 + (size_t)i * HID, sb2 + (size_t)i * HID, i);
        k_fc3_mma<<<BATCH / 64, 256, FC3_SMEM>>>(
            out, tb3 + (size_t)i * NH, sb3 + (size_t)i * NH,
            s_scale + (size_t)i * NH, s_shift + (size_t)i * NH, i, i0off);
    }
}

// round 14
// speedup vs baseline: 1.4361x; 1.0591x over previous
#include <cuda_runtime.h>
#include <cuda_bf16.h>
#include <cstdint>
#include <math.h>

#define BATCH 16384
#define NDIMS 64
#define NH 32
#define HID 512
#define NL 8

// ---------------------------------------------------------------------------
// Scratch (device globals; no allocations allowed)
// ---------------------------------------------------------------------------
__device__ __nv_bfloat16 g_a1hi[BATCH * 1024];      // h1 split hi  [m][1024]
__device__ __nv_bfloat16 g_a1lo[BATCH * 1024];
__device__ __nv_bfloat16 g_a2hi[BATCH * 1024];      // h2 split hi  [m][1024]
__device__ __nv_bfloat16 g_a2lo[BATCH * 1024];
__device__ __nv_bfloat16 g_w1hi[NL * 1024 * NH];    // W1^T split [l][n][k=32]
__device__ __nv_bfloat16 g_w1lo[NL * 1024 * NH];
__device__ __nv_bfloat16 g_w2hi[NL * 1024 * HID];   // W2^T split [l][n][k=512]
__device__ __nv_bfloat16 g_w2lo[NL * 1024 * HID];
__device__ __nv_bfloat16 g_w3hi[NL * 64 * HID];     // W3 dense [l][n=64][k=512]
__device__ __nv_bfloat16 g_w3lo[NL * 64 * HID];     //  rows 0-31: tW3^T, 32-63: sW3^T
__device__ float g_z[2 * BATCH * 32];               // z planes: [parity][m][32]
__device__ float g_ld[2 * BATCH * 32];              // log_det planes

// ---------------------------------------------------------------------------
// PTX helpers (sm_80-level features only: cp.async + mma.sync + ldmatrix)
// ---------------------------------------------------------------------------
__device__ __forceinline__ uint32_t smem_u32(const void* p) {
    uint32_t a;
    asm("{ .reg .u64 t; cvta.to.shared.u64 t, %1; cvt.u32.u64 %0, t; }" : "=r"(a) : "l"(p));
    return a;
}
__device__ __forceinline__ void cp16(uint32_t dst, const void* src) {
    asm volatile("cp.async.cg.shared.global [%0], [%1], 16;" :: "r"(dst), "l"(src));
}
#define CP_COMMIT() asm volatile("cp.async.commit_group;" ::: "memory")
#define CP_WAIT(n)  asm volatile("cp.async.wait_group %0;" :: "n"(n) : "memory")

// non-volatile: register-only op, lets ptxas schedule/interleave MMAs.
__device__ __forceinline__ void mma_bf16(float* d, const uint32_t* a, const uint32_t* b) {
    asm("mma.sync.aligned.m16n8k16.row.col.f32.bf16.bf16.f32 "
        "{%0,%1,%2,%3}, {%4,%5,%6,%7}, {%8,%9}, {%0,%1,%2,%3};"
        : "+f"(d[0]), "+f"(d[1]), "+f"(d[2]), "+f"(d[3])
        : "r"(a[0]), "r"(a[1]), "r"(a[2]), "r"(a[3]), "r"(b[0]), "r"(b[1]));
}
#define LDSM_X4(r0, r1, r2, r3, addr)                                          \
    asm volatile("ldmatrix.sync.aligned.m8n8.x4.shared.b16 {%0,%1,%2,%3}, [%4];" \
        : "=r"(r0), "=r"(r1), "=r"(r2), "=r"(r3) : "r"(addr))

__device__ __forceinline__ void split_bf16(float v, __nv_bfloat16& hi, __nv_bfloat16& lo) {
    hi = __float2bfloat16(v);
    lo = __float2bfloat16(v - __bfloat162float(hi));
}

#define ROWB 80                     // padded row stride in bytes (40 halves)

// ---------------------------------------------------------------------------
// Init: z planes from y, log_det planes = 0. (plane 0 = even cols, 1 = odd)
// ---------------------------------------------------------------------------
__global__ __launch_bounds__(256) void k_init(const float* __restrict__ y) {
    int i = blockIdx.x * 256 + threadIdx.x;
    if (i < BATCH * 32) {
        int m = i >> 5, c = i & 31;
        g_z[i] = y[m * NDIMS + 2 * c];
        g_z[BATCH * 32 + i] = y[m * NDIMS + 2 * c + 1];
        g_ld[i] = 0.0f;
        g_ld[BATCH * 32 + i] = 0.0f;
    }
}

// ---------------------------------------------------------------------------
// Final pack: interleave z/log_det planes into out.
// out[:B*64] = z, out[B*64:] = log_det
// ---------------------------------------------------------------------------
__global__ __launch_bounds__(256) void k_pack(float* __restrict__ out) {
    int i = blockIdx.x * 256 + threadIdx.x;
    if (i >= BATCH * NDIMS) return;
    int m = i >> 6, col = i & 63;
    int p = col & 1, c = col >> 1;
    size_t src = (size_t)p * (BATCH * 32) + m * 32 + c;
    out[i] = g_z[src];
    out[BATCH * NDIMS + i] = g_ld[src];
}

// ---------------------------------------------------------------------------
// Coalesced transpose+split kernels (32x32 smem tiles).
// ---------------------------------------------------------------------------
// W1: src [l][k=32][nn=512] (t or s) -> dst [l][half*512+nn][k=32]
__global__ __launch_bounds__(256) void k_tsplit_w1(const float* __restrict__ tW1,
                                                   const float* __restrict__ sW1) {
    __shared__ float t[32][33];
    int l = blockIdx.z >> 1, half = blockIdx.z & 1;
    int n0 = blockIdx.x * 32;
    const float* W = (half ? sW1 : tW1) + (size_t)l * NH * HID;
    #pragma unroll
    for (int r = threadIdx.y; r < 32; r += 8)
        t[r][threadIdx.x] = W[r * HID + n0 + threadIdx.x];      // k=r, nn coalesced
    __syncthreads();
    #pragma unroll
    for (int r = threadIdx.y; r < 32; r += 8) {
        float v = t[threadIdx.x][r];                            // k=tx, nn=n0+r
        size_t di = (size_t)l * 1024 * NH + (size_t)(half * 512 + n0 + r) * NH + threadIdx.x;
        __nv_bfloat16 hi, lo; split_bf16(v, hi, lo);
        g_w1hi[di] = hi; g_w1lo[di] = lo;
    }
}

// W2: src [l][k=512][nn=512] -> dst [l][half*512+nn][k=512]
__global__ __launch_bounds__(256) void k_tsplit_w2(const float* __restrict__ tW2,
                                                   const float* __restrict__ sW2) {
    __shared__ float t[32][33];
    int l = blockIdx.z >> 1, half = blockIdx.z & 1;
    int k0 = blockIdx.y * 32, n0 = blockIdx.x * 32;
    const float* W = (half ? sW2 : tW2) + (size_t)l * HID * HID;
    #pragma unroll
    for (int r = threadIdx.y; r < 32; r += 8)
        t[r][threadIdx.x] = W[(size_t)(k0 + r) * HID + n0 + threadIdx.x];
    __syncthreads();
    #pragma unroll
    for (int r = threadIdx.y; r < 32; r += 8) {
        float v = t[threadIdx.x][r];                            // k=k0+tx, nn=n0+r
        size_t di = (size_t)l * 1024 * HID + (size_t)(half * 512 + n0 + r) * HID + k0 + threadIdx.x;
        __nv_bfloat16 hi, lo; split_bf16(v, hi, lo);
        g_w2hi[di] = hi; g_w2lo[di] = lo;
    }
}

// W3: src [l][k=512][n=32] -> dst [l][half*32+n][k=512]
__global__ __launch_bounds__(256) void k_tsplit_w3(const float* __restrict__ tW3,
                                                   const float* __restrict__ sW3) {
    __shared__ float t[32][33];
    int l = blockIdx.z >> 1, half = blockIdx.z & 1;
    int k0 = blockIdx.y * 32;
    const float* W = (half ? sW3 : tW3) + (size_t)l * HID * NH;
    #pragma unroll
    for (int r = threadIdx.y; r < 32; r += 8)
        t[r][threadIdx.x] = W[(size_t)(k0 + r) * NH + threadIdx.x];  // k=k0+r, n coalesced
    __syncthreads();
    #pragma unroll
    for (int r = threadIdx.y; r < 32; r += 8) {
        float v = t[threadIdx.x][r];                            // k=k0+tx, n=r
        size_t di = (size_t)l * 64 * HID + (size_t)(half * 32 + r) * HID + k0 + threadIdx.x;
        __nv_bfloat16 hi, lo; split_bf16(v, hi, lo);
        g_w3hi[di] = hi; g_w3lo[di] = lo;
    }
}

// ---------------------------------------------------------------------------
// FC1 via mma.sync bf16x3: h1 = relu(z1 @ W1 + b1) -> bf16 hi/lo
// plane < 0: read y interleaved (layer 0, odd cols); else read g_z plane.
// CTA: 256 thr, tile M=128 x N=128, K=32 single-shot. grid: (BATCH/128, 8)
// ---------------------------------------------------------------------------
__global__ __launch_bounds__(256) void k_fc1_mma(
    const float* __restrict__ ybuf,
    const float* __restrict__ tb1, const float* __restrict__ sb1,
    int layer, int plane)
{
    __shared__ __align__(16) char sAh[128 * ROWB];
    __shared__ __align__(16) char sAl[128 * ROWB];
    __shared__ __align__(16) char sBh[128 * ROWB];
    __shared__ __align__(16) char sBl[128 * ROWB];

    const int tid = threadIdx.x;
    const int wid = tid >> 5, lane = tid & 31;
    const int wm = wid >> 1, wn = wid & 1;
    const int qr = lane >> 2, qc = lane & 3;
    const int lr = lane & 7, lg = lane >> 3;

    const int m0 = blockIdx.x * 128;
    const int n0 = blockIdx.y * 128;

    const float* zsrc = (plane < 0) ? ybuf : (g_z + (size_t)plane * (BATCH * 32));
    for (int idx = tid; idx < 128 * 32; idx += 256) {
        int r = idx >> 5, k = idx & 31;
        float v = (plane < 0) ? zsrc[(m0 + r) * NDIMS + 2 * k + 1]
                              : zsrc[(m0 + r) * 32 + k];
        __nv_bfloat16 hi, lo;
        split_bf16(v, hi, lo);
        *(__nv_bfloat16*)(sAh + r * ROWB + k * 2) = hi;
        *(__nv_bfloat16*)(sAl + r * ROWB + k * 2) = lo;
    }
    {
        const __nv_bfloat16* bh = g_w1hi + ((size_t)layer * 1024 + n0) * NH;
        const __nv_bfloat16* bl = g_w1lo + ((size_t)layer * 1024 + n0) * NH;
        for (int idx = tid; idx < 128 * 4; idx += 256) {
            int r = idx >> 2, seg = idx & 3;
            *(uint4*)(sBh + r * ROWB + seg * 16) = *(const uint4*)(bh + r * NH + seg * 8);
            *(uint4*)(sBl + r * ROWB + seg * 16) = *(const uint4*)(bl + r * NH + seg * 8);
        }
    }
    __syncthreads();

    const uint32_t ah = smem_u32(sAh), al = smem_u32(sAl);
    const uint32_t bh = smem_u32(sBh), bl = smem_u32(sBl);
    const uint32_t aOff = (uint32_t)(wm * 32 + lr + (lg & 1) * 8) * ROWB + (lg >> 1) * 16;
    const uint32_t bOff = (uint32_t)(wn * 64 + lr + (lg >> 1) * 8) * ROWB + (lg & 1) * 16;

    float acc[2][8][4];
    #pragma unroll
    for (int mf = 0; mf < 2; mf++)
        #pragma unroll
        for (int nf = 0; nf < 8; nf++)
            #pragma unroll
            for (int j = 0; j < 4; j++) acc[mf][nf][j] = 0.0f;

    #pragma unroll
    for (int ks = 0; ks < 2; ks++) {
        const uint32_t ko = ks * 32;
        uint32_t Ah[2][4], Al[2][4];
        #pragma unroll
        for (int mf = 0; mf < 2; mf++) {
            uint32_t ra = aOff + mf * 16 * ROWB + ko;
            LDSM_X4(Ah[mf][0], Ah[mf][1], Ah[mf][2], Ah[mf][3], ah + ra);
            LDSM_X4(Al[mf][0], Al[mf][1], Al[mf][2], Al[mf][3], al + ra);
        }
        #pragma unroll
        for (int np = 0; np < 4; np++) {
            uint32_t rb = bOff + np * 16 * ROWB + ko;
            uint32_t Bh[4], Bl[4];
            LDSM_X4(Bh[0], Bh[1], Bh[2], Bh[3], bh + rb);
            LDSM_X4(Bl[0], Bl[1], Bl[2], Bl[3], bl + rb);
            #pragma unroll
            for (int h = 0; h < 2; h++)
                #pragma unroll
                for (int mf = 0; mf < 2; mf++)
                    mma_bf16(acc[mf][np * 2 + h], Ah[mf], Bh + h * 2);
            #pragma unroll
            for (int h = 0; h < 2; h++)
                #pragma unroll
                for (int mf = 0; mf < 2; mf++)
                    mma_bf16(acc[mf][np * 2 + h], Ah[mf], Bl + h * 2);
            #pragma unroll
            for (int h = 0; h < 2; h++)
                #pragma unroll
                for (int mf = 0; mf < 2; mf++)
                    mma_bf16(acc[mf][np * 2 + h], Al[mf], Bh + h * 2);
        }
    }

    const float* bias = (n0 < HID) ? tb1 : sb1;
    const int nbase = ((n0 < HID) ? n0 : n0 - HID) + wn * 64;

    #pragma unroll
    for (int mf = 0; mf < 2; mf++) {
        int r0 = m0 + wm * 32 + mf * 16 + qr;
        #pragma unroll
        for (int nf = 0; nf < 8; nf++) {
            int c = nf * 8 + qc * 2;
            float b0 = bias[nbase + c], b1 = bias[nbase + c + 1];
            int col = n0 + wn * 64 + c;
            #pragma unroll
            for (int half = 0; half < 2; half++) {
                int r = r0 + half * 8;
                float v0 = fmaxf(acc[mf][nf][half * 2 + 0] + b0, 0.0f);
                float v1 = fmaxf(acc[mf][nf][half * 2 + 1] + b1, 0.0f);
                __nv_bfloat16 h0, l0, h1, l1;
                split_bf16(v0, h0, l0);
                split_bf16(v1, h1, l1);
                __nv_bfloat162 ph; ph.x = h0; ph.y = h1;
                __nv_bfloat162 pl; pl.x = l0; pl.y = l1;
                *(__nv_bfloat162*)&g_a1hi[(size_t)r * 1024 + col] = ph;
                *(__nv_bfloat162*)&g_a1lo[(size_t)r * 1024 + col] = pl;
            }
        }
    }
}

// ---------------------------------------------------------------------------
// FC2 via mma.sync bf16x3 (round-10 proven config): h2 = relu(h1@W2+b2)
// CTA: 256 thr, tile M=128 x N=128, K-chunk 32, cp.async 2-stage, ldmatrix.
// grid: (BATCH/128, 8)
// ---------------------------------------------------------------------------
#define TILE_SZ  (128 * ROWB)
#define OFF_AH   0
#define OFF_AL   (1 * TILE_SZ)
#define OFF_BH   (2 * TILE_SZ)
#define OFF_BL   (3 * TILE_SZ)
#define STAGE_SZ (4 * TILE_SZ)
#define FC2_SMEM (2 * STAGE_SZ)

__global__ __launch_bounds__(256) void k_fc2_mma(
    const float* __restrict__ tb2, const float* __restrict__ sb2, int layer)
{
    extern __shared__ char sm[];
    const uint32_t smb = smem_u32(sm);

    const int tid = threadIdx.x;
    const int wid = tid >> 5, lane = tid & 31;
    const int wm = wid >> 1, wn = wid & 1;
    const int qr = lane >> 2, qc = lane & 3;
    const int lr = lane & 7, lg = lane >> 3;

    const int m0 = blockIdx.x * 128;
    const int n0 = blockIdx.y * 128;
    const int hsel = (n0 < HID) ? 0 : HID;

    const __nv_bfloat16* wHi = g_w2hi + (size_t)layer * 1024 * HID;
    const __nv_bfloat16* wLo = g_w2lo + (size_t)layer * 1024 * HID;

    auto load_stage = [&](int st, int kb) {
        const uint32_t base = smb + st * STAGE_SZ;
        #pragma unroll
        for (int t = 0; t < 2; t++) {
            int idx = tid + t * 256;
            int r = idx >> 2, seg = idx & 3;
            uint32_t doff = r * ROWB + seg * 16;
            size_t ga = (size_t)(m0 + r) * 1024 + hsel + kb + seg * 8;
            cp16(base + OFF_AH + doff, g_a1hi + ga);
            cp16(base + OFF_AL + doff, g_a1lo + ga);
            size_t gb = (size_t)(n0 + r) * HID + kb + seg * 8;
            cp16(base + OFF_BH + doff, wHi + gb);
            cp16(base + OFF_BL + doff, wLo + gb);
        }
        CP_COMMIT();
    };

    float acc[2][8][4];
    #pragma unroll
    for (int mf = 0; mf < 2; mf++)
        #pragma unroll
        for (int nf = 0; nf < 8; nf++)
            #pragma unroll
            for (int j = 0; j < 4; j++) acc[mf][nf][j] = 0.0f;

    load_stage(0, 0);

    const uint32_t aOff = (uint32_t)(wm * 32 + lr + (lg & 1) * 8) * ROWB + (lg >> 1) * 16;
    const uint32_t bOff = (uint32_t)(wn * 64 + lr + (lg >> 1) * 8) * ROWB + (lg & 1) * 16;

    for (int ch = 0; ch < 16; ch++) {
        const int st = ch & 1;
        if (ch + 1 < 16) { load_stage(st ^ 1, (ch + 1) * 32); CP_WAIT(1); }
        else             { CP_WAIT(0); }
        __syncthreads();

        const uint32_t tb = smb + st * STAGE_SZ;

        #pragma unroll
        for (int ks = 0; ks < 2; ks++) {
            const uint32_t ko = ks * 32;
            uint32_t Ah[2][4], Al[2][4];
            #pragma unroll
            for (int mf = 0; mf < 2; mf++) {
                uint32_t ra = tb + aOff + mf * 16 * ROWB + ko;
                LDSM_X4(Ah[mf][0], Ah[mf][1], Ah[mf][2], Ah[mf][3], OFF_AH + ra);
                LDSM_X4(Al[mf][0], Al[mf][1], Al[mf][2], Al[mf][3], OFF_AL + ra);
            }
            #pragma unroll
            for (int np = 0; np < 4; np++) {
                uint32_t rb = tb + bOff + np * 16 * ROWB + ko;
                uint32_t Bh[4], Bl[4];
                LDSM_X4(Bh[0], Bh[1], Bh[2], Bh[3], OFF_BH + rb);
                LDSM_X4(Bl[0], Bl[1], Bl[2], Bl[3], OFF_BL + rb);
                #pragma unroll
                for (int h = 0; h < 2; h++)
                    #pragma unroll
                    for (int mf = 0; mf < 2; mf++)
                        mma_bf16(acc[mf][np * 2 + h], Ah[mf], Bh + h * 2);
                #pragma unroll
                for (int h = 0; h < 2; h++)
                    #pragma unroll
                    for (int mf = 0; mf < 2; mf++)
                        mma_bf16(acc[mf][np * 2 + h], Ah[mf], Bl + h * 2);
                #pragma unroll
                for (int h = 0; h < 2; h++)
                    #pragma unroll
                    for (int mf = 0; mf < 2; mf++)
                        mma_bf16(acc[mf][np * 2 + h], Al[mf], Bh + h * 2);
            }
        }
        __syncthreads();
    }

    const float* bias = (n0 < HID) ? tb2 : sb2;
    const int nbase = ((n0 < HID) ? n0 : n0 - HID) + wn * 64;

    #pragma unroll
    for (int mf = 0; mf < 2; mf++) {
        int r0 = m0 + wm * 32 + mf * 16 + qr;
        #pragma unroll
        for (int nf = 0; nf < 8; nf++) {
            int c = nf * 8 + qc * 2;
            float b0 = bias[nbase + c], b1 = bias[nbase + c + 1];
            int col = n0 + wn * 64 + c;
            #pragma unroll
            for (int half = 0; half < 2; half++) {
                int r = r0 + half * 8;
                float v0 = fmaxf(acc[mf][nf][half * 2 + 0] + b0, 0.0f);
                float v1 = fmaxf(acc[mf][nf][half * 2 + 1] + b1, 0.0f);
                __nv_bfloat16 h0, l0, h1, l1;
                split_bf16(v0, h0, l0);
                split_bf16(v1, h1, l1);
                __nv_bfloat162 ph; ph.x = h0; ph.y = h1;
                __nv_bfloat162 pl; pl.x = l0; pl.y = l1;
                *(__nv_bfloat162*)&g_a2hi[(size_t)r * 1024 + col] = ph;
                *(__nv_bfloat162*)&g_a2lo[(size_t)r * 1024 + col] = pl;
            }
        }
    }
}

// ---------------------------------------------------------------------------
// FC3 via mma.sync bf16x3 + coupling epilogue (planar z/log_det).
// DENSE dual-GEMM, M=64 tiles; CTA: 256 thr, 16 K-chunks of 32,
// cp.async 3-stage single-barrier pipeline, ldmatrix. grid: BATCH/64 = 256.
// ---------------------------------------------------------------------------
#define F3_TILE  (64 * ROWB)                   // 5120
#define F3_AHT   0
#define F3_ALT   (1 * F3_TILE)
#define F3_AHS   (2 * F3_TILE)
#define F3_ALS   (3 * F3_TILE)
#define F3_BH    (4 * F3_TILE)
#define F3_BL    (5 * F3_TILE)
#define F3_STAGE (6 * F3_TILE)                 // 30720
#define FC3_SMEM (3 * F3_STAGE)                // 92160

__global__ __launch_bounds__(256) void k_fc3_mma(
    const float* __restrict__ tb3, const float* __restrict__ sb3,
    const float* __restrict__ s_scale, const float* __restrict__ s_shift,
    int layer, int i0p)
{
    extern __shared__ char sm[];
    const uint32_t smb = smem_u32(sm);

    const int tid = threadIdx.x;
    const int wid = tid >> 5, lane = tid & 31;
    const int wm = wid >> 1, wn = wid & 1;
    const int qr = lane >> 2, qc = lane & 3;
    const int lr = lane & 7, lg = lane >> 3;

    const int m0 = blockIdx.x * 64;
    const __nv_bfloat16* wHi = g_w3hi + (size_t)layer * 64 * HID;
    const __nv_bfloat16* wLo = g_w3lo + (size_t)layer * 64 * HID;

    const int ldr = tid >> 2, lds = tid & 3;
    auto load_stage = [&](int st, int kb) {
        const uint32_t base = smb + st * F3_STAGE;
        uint32_t doff = ldr * ROWB + lds * 16;
        size_t gt = (size_t)(m0 + ldr) * 1024 + kb + lds * 8;
        cp16(base + F3_AHT + doff, g_a2hi + gt);
        cp16(base + F3_ALT + doff, g_a2lo + gt);
        size_t gs = gt + HID;
        cp16(base + F3_AHS + doff, g_a2hi + gs);
        cp16(base + F3_ALS + doff, g_a2lo + gs);
        size_t gb = (size_t)ldr * HID + kb + lds * 8;
        cp16(base + F3_BH + doff, wHi + gb);
        cp16(base + F3_BL + doff, wLo + gb);
        CP_COMMIT();
    };

    float acc[4][4];
    #pragma unroll
    for (int nf = 0; nf < 4; nf++)
        #pragma unroll
        for (int j = 0; j < 4; j++) acc[nf][j] = 0.0f;

    load_stage(0, 0);
    load_stage(1, 32);
    CP_WAIT(1);
    __syncthreads();

    const uint32_t aSelH = wn ? F3_AHS : F3_AHT;
    const uint32_t aSelL = wn ? F3_ALS : F3_ALT;
    const uint32_t aOff = (uint32_t)(wm * 16 + lr + (lg & 1) * 8) * ROWB + (lg >> 1) * 16;
    const uint32_t bOff = (uint32_t)(wn * 32 + lr + (lg >> 1) * 8) * ROWB + (lg & 1) * 16;

    int st = 0;
    for (int ch = 0; ch < 16; ch++) {
        if (ch + 2 < 16) {
            int st2 = st + 2; if (st2 >= 3) st2 -= 3;
            load_stage(st2, (ch + 2) * 32);
        }

        const uint32_t tb = smb + st * F3_STAGE;

        #pragma unroll
        for (int ks = 0; ks < 2; ks++) {
            const uint32_t ko = ks * 32;
            uint32_t Ah[4], Al[4];
            {
                uint32_t ra = tb + aOff + ko;
                LDSM_X4(Ah[0], Ah[1], Ah[2], Ah[3], aSelH + ra);
                LDSM_X4(Al[0], Al[1], Al[2], Al[3], aSelL + ra);
            }
            #pragma unroll
            for (int np = 0; np < 2; np++) {
                uint32_t rb = tb + bOff + np * 16 * ROWB + ko;
                uint32_t Bh[4], Bl[4];
                LDSM_X4(Bh[0], Bh[1], Bh[2], Bh[3], F3_BH + rb);
                LDSM_X4(Bl[0], Bl[1], Bl[2], Bl[3], F3_BL + rb);
                #pragma unroll
                for (int h = 0; h < 2; h++)
                    mma_bf16(acc[np * 2 + h], Ah, Bh + h * 2);
                #pragma unroll
                for (int h = 0; h < 2; h++)
                    mma_bf16(acc[np * 2 + h], Ah, Bl + h * 2);
                #pragma unroll
                for (int h = 0; h < 2; h++)
                    mma_bf16(acc[np * 2 + h], Al, Bh + h * 2);
            }
        }

        if (ch + 2 < 16)      CP_WAIT(1);
        else if (ch + 1 < 16) CP_WAIT(0);
        __syncthreads();

        if (++st == 3) st = 0;
    }

    // Stage raw t/s to smem: stg[m_local][c], c 0..63 (t from wn=0, s from wn=1)
    float* stg = (float*)sm;
    {
        int rl0 = wm * 16 + qr;
        #pragma unroll
        for (int nf = 0; nf < 4; nf++) {
            int c = wn * 32 + nf * 8 + qc * 2;
            *(float2*)&stg[rl0 * 64 + c]       = *(float2*)&acc[nf][0];
            *(float2*)&stg[(rl0 + 8) * 64 + c] = *(float2*)&acc[nf][2];
        }
    }
    __syncthreads();

    // Coupling epilogue on dense planes: 64 rows x 32 cols, 8 per thread
    float* zp = g_z + (size_t)i0p * (BATCH * 32);
    float* lp = g_ld + (size_t)i0p * (BATCH * 32);
    #pragma unroll
    for (int q = 0; q < 8; q++) {
        int idx = tid + q * 256;
        int rl = idx >> 5, c = idx & 31;
        int m = m0 + rl;
        float tval = stg[rl * 64 + c] + tb3[c];
        float sraw = stg[rl * 64 + 32 + c] + sb3[c];
        float s = tanhf(sraw) * s_scale[c] + s_shift[c];
        size_t zi = (size_t)m * 32 + c;
        float z0 = zp[zi];
        zp[zi] = z0 * expf(s) + tval;
        lp[zi] += s;
    }
}

// ---------------------------------------------------------------------------
// Launch. Order puts first k_fc2_mma at launch index 3 (the ncu-profiled slot).
// ---------------------------------------------------------------------------
extern "C" void kernel_launch(void* const* d_in, const int* in_sizes, int n_in,
                              void* d_out, int out_size) {
    const float* y       = (const float*)d_in[0];
    const float* tW1     = (const float*)d_in[1];
    const float* tb1     = (const float*)d_in[2];
    const float* tW2     = (const float*)d_in[3];
    const float* tb2     = (const float*)d_in[4];
    const float* tW3     = (const float*)d_in[5];
    const float* tb3     = (const float*)d_in[6];
    const float* sW1     = (const float*)d_in[7];
    const float* sb1     = (const float*)d_in[8];
    const float* sW2     = (const float*)d_in[9];
    const float* sb2     = (const float*)d_in[10];
    const float* sW3     = (const float*)d_in[11];
    const float* sb3     = (const float*)d_in[12];
    const float* s_scale = (const float*)d_in[13];
    const float* s_shift = (const float*)d_in[14];
    float* out = (float*)d_out;

    cudaFuncSetAttribute(k_fc2_mma, cudaFuncAttributeMaxDynamicSharedMemorySize, FC2_SMEM);
    cudaFuncSetAttribute(k_fc3_mma, cudaFuncAttributeMaxDynamicSharedMemorySize, FC3_SMEM);

    const dim3 g1(BATCH / 128, 1024 / 128);
    const dim3 g2(BATCH / 128, 1024 / 128);
    const dim3 tb(32, 8);

    // 0: W1 split, 1: FC1 layer0 (reads y odd cols), 2: W2 split, 3: FC2 layer0
    k_tsplit_w1<<<dim3(16, 1, 2 * NL), tb>>>(tW1, sW1);
    k_fc1_mma<<<g1, 256>>>(y, tb1, sb1, 0, /*plane=*/-1);
    k_tsplit_w2<<<dim3(16, 16, 2 * NL), tb>>>(tW2, sW2);
    k_fc2_mma<<<g2, 256, FC2_SMEM>>>(tb2, sb2, 0);
    // 4-6: init planes, W3 split, FC3 layer0
    k_init<<<(BATCH * 32 + 255) / 256, 256>>>(y);
    k_tsplit_w3<<<dim3(1, 16, 2 * NL), tb>>>(tW3, sW3);
    k_fc3_mma<<<BATCH / 64, 256, FC3_SMEM>>>(tb3, sb3, s_scale, s_shift, 0, /*i0p=*/0);

    for (int i = 1; i < NL; i++) {
        const int p = i & 1;
        const int i0p = p ? 1 : 0;
        const int i1p = p ? 0 : 1;

        k_fc1_mma<<<g1, 256>>>(y, tb1 + (size_t)i * HID, sb1 + (size_t)i * HID, i, i1p);
        k_fc2_mma<<<g2, 256, FC2_SMEM>>>(tb2 + (size_t)i * HID, sb2 + (size_t)i * HID, i);
        k_fc3_mma<<<BATCH / 64, 256, FC3_SMEM>>>(
            tb3 + (size_t)i * NH, sb3 + (size_t)i * NH,
            s_scale + (size_t)i * NH, s_shift + (size_t)i * NH, i, i0p);
    }

    k_pack<<<(BATCH * NDIMS + 255) / 256, 256>>>(out);
}